// round 12
// baseline (speedup 1.0000x reference)
#include <cuda_runtime.h>

// Problem constants
#define T_STEPS 512
#define B_TOTAL 512
#define I_DIM   32
#define H_DIM   64
#define G_DIM   256   // 4*H
#define HX_DIM  96    // concatenated [h(64); x(32)]
#define NT      8     // num tickers

typedef unsigned long long u64;

__device__ __forceinline__ u64 ffma2(u64 a, u64 b, u64 c) {
    u64 d;
    asm("fma.rn.f32x2 %0, %1, %2, %3;" : "=l"(d) : "l"(a), "l"(b), "l"(c));
    return d;
}
__device__ __forceinline__ u64 mul2(u64 a, u64 b) {
    u64 d;
    asm("mul.rn.f32x2 %0, %1, %2;" : "=l"(d) : "l"(a), "l"(b));
    return d;
}
__device__ __forceinline__ u64 add2(u64 a, u64 b) {
    u64 d;
    asm("add.rn.f32x2 %0, %1, %2;" : "=l"(d) : "l"(a), "l"(b));
    return d;
}
__device__ __forceinline__ u64 pack2(float lo, float hi) {
    u64 d;
    asm("mov.b64 %0, {%1, %2};" : "=l"(d) : "f"(lo), "f"(hi));
    return d;
}
__device__ __forceinline__ void unpack2(u64 v, float& lo, float& hi) {
    asm("mov.b64 {%0, %1}, %2;" : "=f"(lo), "=f"(hi) : "l"(v));
}
__device__ __forceinline__ float ex2f(float x) {
    float r;
    asm("ex2.approx.f32 %0, %1;" : "=f"(r) : "f"(x));
    return r;
}
__device__ __forceinline__ float rcpf(float x) {
    float r;
    asm("rcp.approx.f32 %0, %1;" : "=f"(r) : "f"(x));
    return r;
}
#define L2E 1.4426950408889634f

// ---------------------------------------------------------------------------
// Fused LSTM, 8-warps-per-SMSP k-split edition.
// 256 CTAs x 512 threads, 2 batches/CTA, __launch_bounds__(512,2) ->
// 1024 threads/SM = 8 warps/SMSP (2x every previous round).
// Thread (gq = tid&3, kh = (tid>>2)&1, cell = tid>>3) owns HALF of gate row
// gq*64+cell (dims [48*kh, 48*kh+48) of [W_hh|W_ih]):
//   - 24 weight u64 in regs (48 regs -> ~64 total, fits 2 CTAs/SM exactly)
//   - matvec: 2 chains (batch 0/1), 12 ulonglong2 LDS each; the two kh
//     broadcast addresses hit disjoint banks -> still 1 wavefront/LDS
//   - k-reduce: ONE u64 shfl_xor(4) + add2 (both batches packed)
//   - activation y = A*rcp(1+ex2(S*x))+B in-register, redundant in both kh
//     lanes (free); quad combine via 3 independent shfl_xor (1,2,3)
//   - lane gq==0,kh==0 writes h to the next buffer; ONE barrier per step
//   - x staged by gq==1,kh==1 lanes, depth-2 register prefetch ring
// ---------------------------------------------------------------------------
__global__ __launch_bounds__(512, 2) void fused_lstm_kernel(
    const float* __restrict__ x,    const float* __restrict__ w_ih,
    const float* __restrict__ w_hh, const float* __restrict__ b_ih,
    const float* __restrict__ b_hh, const float* __restrict__ w_fc,
    const float* __restrict__ b_fc, float* __restrict__ out)
{
    __shared__ __align__(16) float hx[2][2][HX_DIM];  // [buf][batch][dim]

    const int tid  = threadIdx.x;
    const int gq   = tid & 3;           // 0:i 1:f 2:g 3:o
    const int kh   = (tid >> 2) & 1;    // k-half
    const int cell = tid >> 3;          // 0..63
    const int row  = gq * 64 + cell;    // gate row, PyTorch i,f,g,o order
    const int B0   = blockIdx.x * 2;

    // ---- weights for dims [48*kh, 48*kh+48) of row, k-pair packed ----
    u64 w2[24];
    {
        const float* rh = w_hh + row * H_DIM;
        const float* ri = w_ih + row * I_DIM;
        #pragma unroll
        for (int k = 0; k < 24; k++) {
            int d0 = 48 * kh + 2 * k;
            float a = (d0 < H_DIM)     ? rh[d0]         : ri[d0 - H_DIM];
            float b = (d0 + 1 < H_DIM) ? rh[d0 + 1]     : ri[d0 + 1 - H_DIM];
            w2[k] = pack2(a, b);
        }
    }
    const float bias = (kh == 0) ? (b_ih[row] + b_hh[row]) : 0.0f;

    // ---- per-lane activation constants: y = A*rcp(1 + ex2(S*x)) + B ----
    const float A  = (gq == 2) ? -2.0f       : 1.0f;
    const float S  = (gq == 2) ?  2.0f * L2E : -L2E;
    const float Bc = (gq == 2) ?  1.0f       : 0.0f;

    // ---- x staging: gq==1 && kh==1 lanes (tid&7 == 5), 64 per CTA ----
    const bool is_stage = ((tid & 7) == 5);
    const int  bq = cell >> 5, iq = cell & 31;
    const float* sx = x + ((size_t)(B0 + bq) * T_STEPS) * I_DIM + iq;
    float xr0 = 0.f, xr1 = 0.f;

    // ---- init buf0: h = 0, x(0); preload x(1), x(2) into the ring ----
    if (tid < 128) hx[0][tid >> 6][tid & 63] = 0.0f;
    if (is_stage) {
        hx[0][bq][H_DIM + iq] = sx[0];
        xr0 = sx[1 * I_DIM];
        xr1 = sx[2 * I_DIM];
    }
    u64 c2 = 0ULL;   // cell state (valid on gq==0 lanes; tracked redundantly)
    __syncthreads();

    for (int t = 0; t < T_STEPS; t++) {
        const u64* v0 = (const u64*)hx[t & 1][0] + 24 * kh;
        const u64* v1 = (const u64*)hx[t & 1][1] + 24 * kh;

        // ---- half-row dots: 24 ffma2 per batch, 2 indep chains ----
        u64 acc0 = pack2(bias, 0.0f), acc1 = pack2(bias, 0.0f);
        #pragma unroll
        for (int k = 0; k < 24; k += 2) {
            ulonglong2 a = *(const ulonglong2*)(v0 + k);
            ulonglong2 b = *(const ulonglong2*)(v1 + k);
            acc0 = ffma2(w2[k], a.x, acc0); acc0 = ffma2(w2[k + 1], a.y, acc0);
            acc1 = ffma2(w2[k], b.x, acc1); acc1 = ffma2(w2[k + 1], b.y, acc1);
        }
        float l0, h0, l1, h1;
        unpack2(acc0, l0, h0);
        unpack2(acc1, l1, h1);
        u64 y2 = pack2(l0 + h0, l1 + h1);            // {batch0, batch1} partials

        // ---- k-reduce across kh partner (lane ^ 4): ONE u64 shfl ----
        y2 = add2(y2, __shfl_xor_sync(0xffffffffu, y2, 4));
        float G0, G1;
        unpack2(y2, G0, G1);

        // ---- cheap activation (2 MUFU + 2 alu per batch) ----
        float y0 = A * rcpf(1.0f + ex2f(S * G0)) + Bc;
        float y1 = A * rcpf(1.0f + ex2f(S * G1)) + Bc;
        u64 y = pack2(y0, y1);

        // ---- quad combine: 3 independent shfls (gq bits 0-1 of lane) ----
        u64 fv = __shfl_xor_sync(0xffffffffu, y, 1);  // gq0: f
        u64 gv = __shfl_xor_sync(0xffffffffu, y, 2);  // gq0: g
        u64 ov = __shfl_xor_sync(0xffffffffu, y, 3);  // gq0: o
        c2 = ffma2(fv, c2, mul2(y, gv));              // gq0: c' = f*c + i*g
        float cl, ch;
        unpack2(c2, cl, ch);
        float tl = -2.0f * rcpf(1.0f + ex2f(2.0f * L2E * cl)) + 1.0f;
        float th = -2.0f * rcpf(1.0f + ex2f(2.0f * L2E * ch)) + 1.0f;
        u64 h2 = mul2(ov, pack2(tl, th));             // gq0: h = o*tanh(c')

        // ---- write next buffer; x stage rides the same phase ----
        float* nb0 = hx[(t + 1) & 1][0];
        float* nb1 = hx[(t + 1) & 1][1];
        if ((tid & 7) == 0) {                         // gq==0 && kh==0
            float hl, hh;
            unpack2(h2, hl, hh);
            nb0[cell] = hl;
            nb1[cell] = hh;
        } else if (is_stage) {
            if (t + 1 < T_STEPS) hx[(t + 1) & 1][bq][H_DIM + iq] = xr0;
            xr0 = xr1;
            if (t + 3 < T_STEPS) xr1 = sx[(size_t)(t + 3) * I_DIM];
        }

        __syncthreads();   // single barrier per step
    }

    // ---- final FC: h_last lives in buf[0] (T even) ----
    if (tid < 2 * NT) {
        int b = tid >> 3, n = tid & 7;
        float s = b_fc[n];
        const float* wf = w_fc + n * H_DIM;
        #pragma unroll
        for (int k = 0; k < H_DIM; k++) s += hx[0][b][k] * wf[k];
        out[(B0 + b) * NT + n] = s;
    }
}

// ---------------------------------------------------------------------------
extern "C" void kernel_launch(void* const* d_in, const int* in_sizes, int n_in,
                              void* d_out, int out_size)
{
    const float* x    = (const float*)d_in[0];
    const float* w_ih = (const float*)d_in[1];
    const float* w_hh = (const float*)d_in[2];
    const float* b_ih = (const float*)d_in[3];
    const float* b_hh = (const float*)d_in[4];
    const float* w_fc = (const float*)d_in[5];
    const float* b_fc = (const float*)d_in[6];
    float* out = (float*)d_out;

    (void)in_sizes; (void)n_in; (void)out_size;

    fused_lstm_kernel<<<B_TOTAL / 2, 512>>>(x, w_ih, w_hh, b_ih, b_hh,
                                            w_fc, b_fc, out);
}

// round 13
// speedup vs baseline: 1.7159x; 1.7159x over previous
#include <cuda_runtime.h>

// Problem constants
#define T_STEPS 512
#define B_TOTAL 512
#define I_DIM   32
#define H_DIM   64
#define G_DIM   256   // 4*H
#define HX_DIM  96    // concatenated [h(64); x(32)]
#define NT      8     // num tickers

__device__ __forceinline__ float ex2f(float x) {
    float r;
    asm("ex2.approx.f32 %0, %1;" : "=f"(r) : "f"(x));
    return r;
}
__device__ __forceinline__ float rcpf(float x) {
    float r;
    asm("rcp.approx.f32 %0, %1;" : "=f"(r) : "f"(x));
    return r;
}
#define L2E 1.4426950408889634f
__device__ __forceinline__ float sigm_fast(float x) {       // 1/(1+e^-x)
    return rcpf(1.0f + ex2f(-L2E * x));
}
__device__ __forceinline__ float tanh_fast2(float x) {      // 1 - 2/(e^2x+1)
    return 1.0f - 2.0f * rcpf(1.0f + ex2f(2.0f * L2E * x));
}

// ---------------------------------------------------------------------------
// Fused LSTM, scalar-FFMA / ptxas-scheduled edition.
// 256 CTAs x 256 threads, 2 batches/CTA, 2 CTAs/SM (launch_bounds(256,2)).
// Thread g owns ONE gate row of [W_hh | W_ih] (96 float regs, plain C++ FFMA
// so ptxas owns banking/.reuse/scheduling). Operands hx[b][96] in natural
// layout, loaded as float4 (warp-broadcast LDS.128, conflict-free).
// Elementwise (threads 0..127) uses raw ex2/rcp MUFU activations (~4 instr
// per gate instead of IEEE-div expansions). x staged by threads 128..191
// via a depth-4 register prefetch ring. Two barriers per step (proven
// non-binding). The co-resident CTA fills tail/barrier dead time.
// ---------------------------------------------------------------------------
__global__ __launch_bounds__(256, 2) void fused_lstm_kernel(
    const float* __restrict__ x,    const float* __restrict__ w_ih,
    const float* __restrict__ w_hh, const float* __restrict__ b_ih,
    const float* __restrict__ b_hh, const float* __restrict__ w_fc,
    const float* __restrict__ b_fc, float* __restrict__ out)
{
    __shared__ __align__(16) float hx[2][HX_DIM];   // [b][0:64)=h, [64:96)=x
    __shared__ __align__(16) float gates[2][G_DIM]; // [b][g]

    const int tid = threadIdx.x;
    const int g   = tid;                 // gate row
    const int B0  = blockIdx.x * 2;

    // ---- weights for row g: [W_hh(64) | W_ih(32)] in 96 float regs ----
    float w[HX_DIM];
    {
        const float* rh = w_hh + g * H_DIM;
        #pragma unroll
        for (int k = 0; k < H_DIM; k++) w[k] = rh[k];
        const float* ri = w_ih + g * I_DIM;
        #pragma unroll
        for (int i = 0; i < I_DIM; i++) w[H_DIM + i] = ri[i];
    }
    const float bias = b_ih[g] + b_hh[g];

    // ---- elementwise identity: threads 0..127 own cell (be, ke) ----
    const int be = tid >> 6;             // valid for tid < 128
    const int ke = tid & 63;
    float c_val = 0.0f;

    // ---- staging identity: threads 128..191 stage x (bq, iq) ----
    const int  st = tid - 128;
    const bool is_stage = (st >= 0) && (st < 64);
    const int  bq = (st >> 5) & 1, iq = st & 31;
    const float* sx = x + ((size_t)(B0 + bq) * T_STEPS) * I_DIM + iq;
    float xr0 = 0.f, xr1 = 0.f, xr2 = 0.f;

    // ---- init: h = 0, x(0) staged, x(1..3) in regs ----
    if (tid < 128) hx[be][ke] = 0.0f;
    if (is_stage) {
        hx[bq][H_DIM + iq] = sx[0];
        xr0 = sx[1 * I_DIM];
        xr1 = sx[2 * I_DIM];
        xr2 = sx[3 * I_DIM];
    }
    __syncthreads();

    const float4* v0 = (const float4*)hx[0];
    const float4* v1 = (const float4*)hx[1];

    for (int t = 0; t < T_STEPS; t++) {
        // ---- scalar matvec: 96-dim [h;x] dots, both batches ----
        // Plain C++ FFMA chains; float4 loads; ptxas schedules/banks.
        float a0 = bias, a1 = bias;
        float b0 = 0.f,  b1 = 0.f;        // split accumulators for ILP
        #pragma unroll
        for (int kk = 0; kk < HX_DIM / 8; kk++) {
            float4 p0 = v0[2 * kk];
            float4 p1 = v0[2 * kk + 1];
            float4 q0 = v1[2 * kk];
            float4 q1 = v1[2 * kk + 1];
            const int k = 8 * kk;
            a0 = fmaf(w[k + 0], p0.x, a0); a0 = fmaf(w[k + 1], p0.y, a0);
            a0 = fmaf(w[k + 2], p0.z, a0); a0 = fmaf(w[k + 3], p0.w, a0);
            b0 = fmaf(w[k + 4], p1.x, b0); b0 = fmaf(w[k + 5], p1.y, b0);
            b0 = fmaf(w[k + 6], p1.z, b0); b0 = fmaf(w[k + 7], p1.w, b0);
            a1 = fmaf(w[k + 0], q0.x, a1); a1 = fmaf(w[k + 1], q0.y, a1);
            a1 = fmaf(w[k + 2], q0.z, a1); a1 = fmaf(w[k + 3], q0.w, a1);
            b1 = fmaf(w[k + 4], q1.x, b1); b1 = fmaf(w[k + 5], q1.y, b1);
            b1 = fmaf(w[k + 6], q1.z, b1); b1 = fmaf(w[k + 7], q1.w, b1);
        }
        gates[0][g] = a0 + b0;
        gates[1][g] = a1 + b1;

        __syncthreads();   // gates visible; all hx reads of step t complete

        if (tid < 128) {
            // ---- elementwise cell; PyTorch gate order i,f,g,o ----
            float i_a = sigm_fast (gates[be][ke]);
            float f_a = sigm_fast (gates[be][64 + ke]);
            float g_a = tanh_fast2(gates[be][128 + ke]);
            float o_a = sigm_fast (gates[be][192 + ke]);
            c_val = f_a * c_val + i_a * g_a;
            hx[be][ke] = o_a * tanh_fast2(c_val);
        } else if (is_stage) {
            // ---- stage x(t+1) from the ring; refill with x(t+4) ----
            if (t + 1 < T_STEPS) hx[bq][H_DIM + iq] = xr0;
            xr0 = xr1; xr1 = xr2;
            if (t + 4 < T_STEPS) xr2 = sx[(size_t)(t + 4) * I_DIM];
        }

        __syncthreads();   // h(t+1), x(t+1) visible
    }

    // ---- final FC: out[b][n] = h_last[b] . w_fc[n] + b_fc[n] ----
    if (tid < 2 * NT) {
        int b = tid >> 3, n = tid & 7;
        float s = b_fc[n];
        const float* wf = w_fc + n * H_DIM;
        #pragma unroll
        for (int k = 0; k < H_DIM; k++) s += hx[b][k] * wf[k];
        out[(B0 + b) * NT + n] = s;
    }
}

// ---------------------------------------------------------------------------
extern "C" void kernel_launch(void* const* d_in, const int* in_sizes, int n_in,
                              void* d_out, int out_size)
{
    const float* x    = (const float*)d_in[0];
    const float* w_ih = (const float*)d_in[1];
    const float* w_hh = (const float*)d_in[2];
    const float* b_ih = (const float*)d_in[3];
    const float* b_hh = (const float*)d_in[4];
    const float* w_fc = (const float*)d_in[5];
    const float* b_fc = (const float*)d_in[6];
    float* out = (float*)d_out;

    (void)in_sizes; (void)n_in; (void)out_size;

    fused_lstm_kernel<<<B_TOTAL / 2, 256>>>(x, w_ih, w_hh, b_ih, b_hh,
                                            w_fc, b_fc, out);
}